// round 9
// baseline (speedup 1.0000x reference)
#include <cuda_runtime.h>

#define BATCH    16
#define NROWS    25200
#define NCOLS    85
#define MAXDET   300
#define CTHRES   0.25f
#define NTHREADS 512
#define NWARPS   (NTHREADS / 32)   // 16
#define NSLICES  9
#define NGMAX    12                // ceil(68*85 / 512)

// Slice boundaries aligned to 4 slots => slice output base is 16B-aligned
// (4 slots * 85 cols * 4B = 1360B, divisible by 16). Early slices own many
// slots (short scans), late slices few slots (long scans).
__device__ __constant__ int d_clo[NSLICES] = {0, 68, 120, 164, 200, 228, 252, 272, 288};
__device__ __constant__ int d_chi[NSLICES] = {68, 120, 164, 200, 228, 252, 272, 288, 300};
// Scan bound per slice (>=5 sigma margin vs Binomial(u, .75) >= c_hi);
// fallback loop preserves correctness for arbitrary data.
__device__ __constant__ int d_u[NSLICES]   = {160, 256, 320, 352, 400, 416, 432, 448, 464};

__global__ __launch_bounds__(NTHREADS, 2)
void compact_kernel(const float* __restrict__ pred, float* __restrict__ out)
{
    __shared__ int s_order[MAXDET];
    __shared__ int s_cnt[NWARPS];

    const int b     = blockIdx.x / NSLICES;
    const int slice = blockIdx.x % NSLICES;
    const int tid   = threadIdx.x;
    const int lane  = tid & 31;
    const int warp  = tid >> 5;

    const int lo = d_clo[slice];
    const int hi = d_chi[slice];
    const int u  = d_u[slice];
    const unsigned lanemask = (1u << lane) - 1u;

    const float* bpred = pred + (long long)b * NROWS * NCOLS;

    int base;

    // ---- chunk 1: conf scan of rows [0, u) — expected to be the ONLY chunk ----
    {
        bool m = false;
        if (tid < u)
            m = __ldg(&bpred[(long long)tid * NCOLS + 4]) > CTHRES;

        unsigned bal = __ballot_sync(0xffffffffu, m);
        if (lane == 0) s_cnt[warp] = __popc(bal);
        __syncthreads();                        // barrier #1

        // Every warp redundantly scans the 16 warp counts — no 2nd barrier.
        int v = (lane < NWARPS) ? s_cnt[lane] : 0;
        int inc = v;
        #pragma unroll
        for (int o = 1; o < NWARPS; o <<= 1) {
            int t = __shfl_up_sync(0xffffffffu, inc, o);
            if (lane >= o) inc += t;
        }
        int total = __shfl_sync(0xffffffffu, inc, NWARPS - 1);
        int wpre  = (warp == 0) ? 0 : __shfl_sync(0xffffffffu, inc, warp - 1);

        if (m) {
            int rank = wpre + __popc(bal & lanemask);
            if (rank < MAXDET) s_order[rank] = tid;
        }
        base = total;
    }

    // ---- fallback: only if chunk 1 didn't cover this slice (statistically never) ----
    int row0 = u;
    while (base < hi && row0 < NROWS) {
        __syncthreads();
        int i = row0 + tid;
        bool m = false;
        if (i < NROWS)
            m = __ldg(&bpred[(long long)i * NCOLS + 4]) > CTHRES;

        unsigned bal = __ballot_sync(0xffffffffu, m);
        if (lane == 0) s_cnt[warp] = __popc(bal);
        __syncthreads();

        int v = (lane < NWARPS) ? s_cnt[lane] : 0;
        int inc = v;
        #pragma unroll
        for (int o = 1; o < NWARPS; o <<= 1) {
            int t = __shfl_up_sync(0xffffffffu, inc, o);
            if (lane >= o) inc += t;
        }
        int total = __shfl_sync(0xffffffffu, inc, NWARPS - 1);
        int wpre  = (warp == 0) ? 0 : __shfl_sync(0xffffffffu, inc, warp - 1);

        if (m) {
            int rank = base + wpre + __popc(bal & lanemask);
            if (rank < MAXDET) s_order[rank] = i;
        }
        base += total;
        row0 += NTHREADS;
    }
    __syncthreads();        // barrier #2: s_order visible to all warps

    int cnt = base;
    if (cnt > MAXDET) cnt = MAXDET;

    const int nslots = hi - lo;
    const int nelem  = nslots * NCOLS;          // divisible by 4 (nslots % 4 == 0, wait 85 odd)
    // nslots multiple of 4 => nelem = nslots*85 multiple of 4? 4*85=340, yes.
    const int nquad  = nelem >> 2;              // float4 count, exact

    float* bout = out + (long long)b * MAXDET * NCOLS + (long long)lo * NCOLS; // 16B aligned

    // Gather in float4 granularity: quad q covers elements [4q, 4q+4) of the
    // slice. Element e -> slot e/85, col e%85. Scalar gmem loads (rows are
    // 340B-strided, not 16B aligned), vector STG.128 stores.
    #pragma unroll
    for (int k = 0; k < (NGMAX + 3) / 4 + 1; ++k) {   // ceil(nquad/NTHREADS) <= 3
        int q = k * NTHREADS + tid;
        if (q < nquad) {
            int e0 = q << 2;
            float4 v;
            float* vp = (float*)&v;
            int sl  = e0 / NCOLS;
            int col = e0 - sl * NCOLS;
            #pragma unroll
            for (int j = 0; j < 4; ++j) {
                float x = 0.0f;
                int slot = lo + sl;
                if (slot < cnt)
                    x = __ldg(&bpred[(long long)s_order[slot] * NCOLS + col]);
                vp[j] = x;
                if (++col == NCOLS) { col = 0; ++sl; }
            }
            ((float4*)bout)[q] = v;
        }
    }
}

extern "C" void kernel_launch(void* const* d_in, const int* in_sizes, int n_in,
                              void* d_out, int out_size)
{
    const float* pred = (const float*)d_in[0];
    float* out = (float*)d_out;
    compact_kernel<<<BATCH * NSLICES, NTHREADS>>>(pred, out);
}

// round 10
// speedup vs baseline: 1.0435x; 1.0435x over previous
#include <cuda_runtime.h>

#define BATCH    16
#define NROWS    25200
#define NCOLS    85
#define MAXDET   300
#define CTHRES   0.25f
#define NTHREADS 512
#define NWARPS   (NTHREADS / 32)   // 16
#define NSLICES  9
#define NGMAX    11                // ceil(66*85 / 512)

// Balanced slice boundaries: early slices own many slots (short scans),
// late slices few slots (long scans); cost ~ scan_wavefronts + gather equalized.
__device__ __constant__ int d_clo[NSLICES] = {0, 66, 119, 163, 199, 228, 252, 272, 288};
__device__ __constant__ int d_chi[NSLICES] = {66, 119, 163, 199, 228, 252, 272, 288, 300};
// Scan bound per slice: P(Binomial(u, 0.75) < c_hi) is >=5 sigma unlikely for
// the benchmark's uniform inputs; the fallback loop below preserves exact
// correctness for ARBITRARY data — a missed bound only costs extra chunks.
__device__ __constant__ int d_u[NSLICES]   = {160, 256, 320, 352, 400, 416, 432, 448, 464};

__global__ __launch_bounds__(NTHREADS, 2)
void compact_kernel(const float* __restrict__ pred, float* __restrict__ out)
{
    __shared__ int s_order[MAXDET];
    __shared__ int s_cnt[NWARPS];

    const int b     = blockIdx.x / NSLICES;
    const int slice = blockIdx.x % NSLICES;
    const int tid   = threadIdx.x;
    const int lane  = tid & 31;
    const int warp  = tid >> 5;

    const int lo = d_clo[slice];
    const int hi = d_chi[slice];
    const int u  = d_u[slice];
    const unsigned lanemask = (1u << lane) - 1u;

    const float* bpred = pred + (long long)b * NROWS * NCOLS;

    int base;

    // ---- chunk 1: conf scan of rows [0, u) — expected to be the ONLY chunk ----
    {
        bool m = false;
        if (tid < u)
            m = __ldg(&bpred[(long long)tid * NCOLS + 4]) > CTHRES;

        unsigned bal = __ballot_sync(0xffffffffu, m);
        if (lane == 0) s_cnt[warp] = __popc(bal);
        __syncthreads();                        // barrier #1 (only one in scan)

        // Every warp redundantly scans the 16 warp counts — no 2nd barrier.
        int v = (lane < NWARPS) ? s_cnt[lane] : 0;
        int inc = v;
        #pragma unroll
        for (int o = 1; o < NWARPS; o <<= 1) {
            int t = __shfl_up_sync(0xffffffffu, inc, o);
            if (lane >= o) inc += t;
        }
        int total = __shfl_sync(0xffffffffu, inc, NWARPS - 1);
        int wpre  = (warp == 0) ? 0 : __shfl_sync(0xffffffffu, inc, warp - 1);

        if (m) {
            int rank = wpre + __popc(bal & lanemask);
            if (rank < MAXDET) s_order[rank] = tid;
        }
        base = total;
    }

    // ---- fallback: only if chunk 1 didn't cover this slice (statistically never) ----
    int row0 = u;
    while (base < hi && row0 < NROWS) {
        __syncthreads();    // protect s_cnt rewrite vs prior reads
        int i = row0 + tid;
        bool m = false;
        if (i < NROWS)
            m = __ldg(&bpred[(long long)i * NCOLS + 4]) > CTHRES;

        unsigned bal = __ballot_sync(0xffffffffu, m);
        if (lane == 0) s_cnt[warp] = __popc(bal);
        __syncthreads();

        int v = (lane < NWARPS) ? s_cnt[lane] : 0;
        int inc = v;
        #pragma unroll
        for (int o = 1; o < NWARPS; o <<= 1) {
            int t = __shfl_up_sync(0xffffffffu, inc, o);
            if (lane >= o) inc += t;
        }
        int total = __shfl_sync(0xffffffffu, inc, NWARPS - 1);
        int wpre  = (warp == 0) ? 0 : __shfl_sync(0xffffffffu, inc, warp - 1);

        if (m) {
            int rank = base + wpre + __popc(bal & lanemask);
            if (rank < MAXDET) s_order[rank] = i;
        }
        base += total;
        row0 += NTHREADS;
    }
    __syncthreads();        // barrier #2: s_order visible to all warps

    int cnt = base;
    if (cnt > MAXDET) cnt = MAXDET;

    const int nslots = hi - lo;
    float* bout = out + (long long)b * MAXDET * NCOLS + (long long)lo * NCOLS;

    // Gather slots [lo, hi). Scalar, lane-coalesced (consecutive lanes read
    // consecutive columns of the same source row). Division-free: one initial
    // div, then incremental (sl, col) update per step (NTHREADS = 6*85 + 2).
    int sl  = tid / NCOLS;      // 0..6
    int col = tid - sl * NCOLS;

    int  src_k[NGMAX];
    int  col_k[NGMAX];
    bool ok_k[NGMAX];
    {
        int sl_i = sl, col_i = col;
        #pragma unroll
        for (int k = 0; k < NGMAX; ++k) {
            int slot = lo + sl_i;
            ok_k[k]  = (sl_i < nslots) && (slot < cnt);
            col_k[k] = col_i;
            src_k[k] = ok_k[k] ? s_order[slot] : 0;
            sl_i  += 6;
            col_i += 2;
            if (col_i >= NCOLS) { col_i -= NCOLS; sl_i += 1; }
        }
    }
    float v_k[NGMAX];
    #pragma unroll
    for (int k = 0; k < NGMAX; ++k)
        v_k[k] = ok_k[k] ? __ldg(&bpred[(long long)src_k[k] * NCOLS + col_k[k]]) : 0.0f;

    {
        int sl_i = sl, col_i = col;
        int e = tid;
        #pragma unroll
        for (int k = 0; k < NGMAX; ++k) {
            if (sl_i < nslots) bout[e] = v_k[k];
            e     += NTHREADS;
            sl_i  += 6;
            col_i += 2;
            if (col_i >= NCOLS) { col_i -= NCOLS; sl_i += 1; }
        }
    }
}

extern "C" void kernel_launch(void* const* d_in, const int* in_sizes, int n_in,
                              void* d_out, int out_size)
{
    const float* pred = (const float*)d_in[0];
    float* out = (float*)d_out;
    compact_kernel<<<BATCH * NSLICES, NTHREADS>>>(pred, out);
}